// round 9
// baseline (speedup 1.0000x reference)
#include <cuda_runtime.h>
#include <cuda_fp16.h>
#include <math.h>

#define N_NODES 4096
#define F_IN 512
#define H_HEADS 8
#define C_OUT 128
#define HC (H_HEADS * C_OUT)   // 1024
#define ALPHA 0.2f
#define MAX_DEG 1024

// Scratch (allocation-free rule: __device__ globals)
__device__ float g_feats[N_NODES * HC];       // [n][h*128+c], 16 MB (L2-resident)
__device__ float g_sself[H_HEADS * N_NODES];  // [h][n]
__device__ float g_sneigh[H_HEADS * N_NODES]; // [h][n]

// ---------------------------------------------------------------------------
// TF32 tensor-core GEMM + fused score epilogue.
// ---------------------------------------------------------------------------
__device__ __forceinline__ unsigned f2tf32(float x) {
    unsigned u;
    asm("cvt.rna.tf32.f32 %0, %1;" : "=r"(u) : "f"(x));
    return u;
}

__device__ __forceinline__ void mma_tf32(float* c, const unsigned* a, const unsigned* b) {
    asm volatile(
        "mma.sync.aligned.m16n8k8.row.col.f32.tf32.tf32.f32 "
        "{%0,%1,%2,%3}, {%4,%5,%6,%7}, {%8,%9}, {%0,%1,%2,%3};"
        : "+f"(c[0]), "+f"(c[1]), "+f"(c[2]), "+f"(c[3])
        : "r"(a[0]), "r"(a[1]), "r"(a[2]), "r"(a[3]), "r"(b[0]), "r"(b[1]));
}

// packed fp32 FMA (sm_103a): acc = a * b + acc, 2 lanes
__device__ __forceinline__ void ffma2(unsigned long long& acc,
                                      unsigned long long a,
                                      unsigned long long b) {
    asm("fma.rn.f32x2 %0, %1, %2, %0;" : "+l"(acc) : "l"(a), "l"(b));
}

#define AS_STRIDE 36   // bank = (4r + c) % 32 -> conflict-free frag loads
#define BS_STRIDE 136  // bank = (8k + n) % 32 -> conflict-free frag loads

__global__ __launch_bounds__(256) void gemm_kernel(const float* __restrict__ X,
                                                   const float* __restrict__ W,
                                                   const float* __restrict__ a_self,
                                                   const float* __restrict__ a_neigh) {
    __shared__ unsigned As[128][AS_STRIDE];  // [m][k]
    __shared__ unsigned Bs[32][BS_STRIDE];   // [k][n]
    __shared__ float sredS[4][128];
    __shared__ float sredN[4][128];

    const int h  = blockIdx.x;
    const int m0 = blockIdx.y * 128;
    const float* Wh = W + (size_t)h * F_IN * C_OUT;

    const int t    = threadIdx.x;
    const int lane = t & 31;
    const int w    = t >> 5;
    const int warp_m = (w & 1) * 64;
    const int warp_n = (w >> 1) * 32;

    float acc[4][4][4];
#pragma unroll
    for (int mt = 0; mt < 4; mt++)
#pragma unroll
        for (int nt = 0; nt < 4; nt++)
#pragma unroll
            for (int q = 0; q < 4; q++) acc[mt][nt][q] = 0.0f;

    const int a_row  = t >> 3;
    const int a_col4 = (t & 7) * 4;
    const int b_row  = t >> 5;
    const int b_col4 = (t & 31) * 4;

    float4 av[4], bv[4];
#pragma unroll
    for (int p = 0; p < 4; p++) {
        av[p] = *reinterpret_cast<const float4*>(
            X + (size_t)(m0 + a_row + p * 32) * F_IN + a_col4);
        bv[p] = *reinterpret_cast<const float4*>(
            Wh + (size_t)(b_row + p * 8) * C_OUT + b_col4);
    }

    for (int chunk = 0; chunk < F_IN / 32; chunk++) {
        __syncthreads();
#pragma unroll
        for (int p = 0; p < 4; p++) {
            unsigned* ad = &As[a_row + p * 32][a_col4];
            ad[0] = f2tf32(av[p].x); ad[1] = f2tf32(av[p].y);
            ad[2] = f2tf32(av[p].z); ad[3] = f2tf32(av[p].w);
            unsigned* bd = &Bs[b_row + p * 8][b_col4];
            bd[0] = f2tf32(bv[p].x); bd[1] = f2tf32(bv[p].y);
            bd[2] = f2tf32(bv[p].z); bd[3] = f2tf32(bv[p].w);
        }
        __syncthreads();

        if (chunk + 1 < F_IN / 32) {
            const int k0 = (chunk + 1) * 32;
#pragma unroll
            for (int p = 0; p < 4; p++) {
                av[p] = *reinterpret_cast<const float4*>(
                    X + (size_t)(m0 + a_row + p * 32) * F_IN + k0 + a_col4);
                bv[p] = *reinterpret_cast<const float4*>(
                    Wh + (size_t)(k0 + b_row + p * 8) * C_OUT + b_col4);
            }
        }

#pragma unroll
        for (int ks = 0; ks < 32; ks += 8) {
            unsigned afr[4][4], bfr[4][2];
            const int r0 = warp_m + (lane >> 2);
            const int cA = ks + (lane & 3);
#pragma unroll
            for (int mt = 0; mt < 4; mt++) {
                const int r = r0 + mt * 16;
                afr[mt][0] = As[r][cA];
                afr[mt][1] = As[r + 8][cA];
                afr[mt][2] = As[r][cA + 4];
                afr[mt][3] = As[r + 8][cA + 4];
            }
            const int rB = ks + (lane & 3);
            const int nB = warp_n + (lane >> 2);
#pragma unroll
            for (int nt = 0; nt < 4; nt++) {
                bfr[nt][0] = Bs[rB][nB + nt * 8];
                bfr[nt][1] = Bs[rB + 4][nB + nt * 8];
            }
#pragma unroll
            for (int mt = 0; mt < 4; mt++)
#pragma unroll
                for (int nt = 0; nt < 4; nt++)
                    mma_tf32(acc[mt][nt], afr[mt], bfr[nt]);
        }
    }

    // Epilogue: fp32 feats store + fused score reduction
    const int rloc  = warp_m + (lane >> 2);
    const int cloc  = warp_n + (lane & 3) * 2;
    const int cbase = h * C_OUT + cloc;

    float asf[4][2], anf[4][2];
#pragma unroll
    for (int nt = 0; nt < 4; nt++) {
        float2 s2 = *reinterpret_cast<const float2*>(a_self  + h * C_OUT + cloc + nt * 8);
        float2 n2 = *reinterpret_cast<const float2*>(a_neigh + h * C_OUT + cloc + nt * 8);
        asf[nt][0] = s2.x; asf[nt][1] = s2.y;
        anf[nt][0] = n2.x; anf[nt][1] = n2.y;
    }

#pragma unroll
    for (int mt = 0; mt < 4; mt++) {
#pragma unroll
        for (int p = 0; p < 2; p++) {
            const int r = m0 + rloc + mt * 16 + p * 8;
            float ssp = 0.0f, snp = 0.0f;
#pragma unroll
            for (int nt = 0; nt < 4; nt++) {
                const float v0 = acc[mt][nt][2 * p];
                const float v1 = acc[mt][nt][2 * p + 1];
                ssp = fmaf(v0, asf[nt][0], ssp);
                ssp = fmaf(v1, asf[nt][1], ssp);
                snp = fmaf(v0, anf[nt][0], snp);
                snp = fmaf(v1, anf[nt][1], snp);
                *reinterpret_cast<float2*>(g_feats + (size_t)r * HC + cbase + nt * 8) =
                    make_float2(v0, v1);
            }
            ssp += __shfl_xor_sync(0xffffffffu, ssp, 1);
            ssp += __shfl_xor_sync(0xffffffffu, ssp, 2);
            snp += __shfl_xor_sync(0xffffffffu, snp, 1);
            snp += __shfl_xor_sync(0xffffffffu, snp, 2);
            if ((lane & 3) == 0) {
                const int rl = rloc + mt * 16 + p * 8;
                sredS[w >> 1][rl] = ssp;
                sredN[w >> 1][rl] = snp;
            }
        }
    }
    __syncthreads();
    if (t < 128) {
        float ss = sredS[0][t] + sredS[1][t] + sredS[2][t] + sredS[3][t];
        float sn = sredN[0][t] + sredN[1][t] + sredN[2][t] + sredN[3][t];
        g_sself[h * N_NODES + m0 + t]  = ss;
        g_sneigh[h * N_NODES + m0 + t] = sn;
    }
}

// ---------------------------------------------------------------------------
// Aggregation: one CTA per row i.
//  1) direct-to-position compaction: float4 A loads in regs, ballot-count,
//     warp prefix, then write final positions (2 syncs, nbr[] only 1024)
//  2) per-head softmax stats (warp = head), __expf
//  3) 64-neighbor chunks: coef table, paired fp32 gather with packed FFMA2
// ---------------------------------------------------------------------------
__global__ __launch_bounds__(256) void agg_kernel(const float* __restrict__ A,
                                                  const float* __restrict__ bias,
                                                  float* __restrict__ out) {
    __shared__ int   nbr[MAX_DEG];      // 4 KB
    __shared__ int   warp_cnt[8];
    __shared__ float sM[H_HEADS], sInvZ[H_HEADS], sS[H_HEADS];
    __shared__ float coef[64][H_HEADS]; // 2 KB
    __shared__ float red[128][8];       // 4 KB

    const int i    = blockIdx.x;
    const int t    = threadIdx.x;
    const int lane = t & 31;
    const int w    = t >> 5;

    const float* Arow = A + (size_t)i * N_NODES;

    // ---- 1) compaction: count first, then write at final position ----
    float4 v4[4];
    unsigned bal[16];
    {
        const float* Aseg = Arow + (w << 9);  // warp owns 512 cols
#pragma unroll
        for (int b = 0; b < 4; b++)
            v4[b] = reinterpret_cast<const float4*>(Aseg)[(b << 5) + lane];  // MLP=4x16B
        int wcnt = 0;
        const float* vf = reinterpret_cast<const float*>(v4);
#pragma unroll
        for (int s = 0; s < 16; s++) {
            const bool p = (vf[s] != 0.0f);
            bal[s] = __ballot_sync(0xffffffffu, p);
            wcnt += __popc(bal[s]);
        }
        if (lane == 0) warp_cnt[w] = wcnt;
    }
    __syncthreads();

    int pref[9];
    pref[0] = 0;
#pragma unroll
    for (int ww = 0; ww < 8; ww++) pref[ww + 1] = pref[ww] + warp_cnt[ww];
    const int deg = min(pref[8], MAX_DEG);  // >= 1 (self loop)

    {
        const unsigned lmask = (1u << lane) - 1u;
        int running = pref[w];
        const float* vf = reinterpret_cast<const float*>(v4);
#pragma unroll
        for (int s = 0; s < 16; s++) {
            const bool p = (vf[s] != 0.0f);
            if (p) {
                const int pos = running + __popc(bal[s] & lmask);
                const int col = (w << 9) + ((s >> 2) << 7) + (lane << 2) + (s & 3);
                if (pos < MAX_DEG) nbr[pos] = col;
            }
            running += __popc(bal[s]);
        }
    }
    __syncthreads();

    // ---- 2) per-head softmax stats; warp w handles head w ----
    {
        const float ss = g_sself[(w << 12) + i];
        const float* snh = g_sneigh + (w << 12);
        float mx = -INFINITY;
#pragma unroll 4
        for (int k = lane; k < deg; k += 32)
            mx = fmaxf(mx, snh[nbr[k]]);
#pragma unroll
        for (int o = 16; o > 0; o >>= 1)
            mx = fmaxf(mx, __shfl_xor_sync(0xffffffffu, mx, o));
        float e = ss + mx;
        const float Mlogit = (e > 0.0f) ? e : ALPHA * e;  // leaky monotone

        float Z = 0.0f;
#pragma unroll 4
        for (int k = lane; k < deg; k += 32) {
            float x = ss + snh[nbr[k]];
            x = (x > 0.0f) ? x : ALPHA * x;
            Z += __expf(x - Mlogit);
        }
#pragma unroll
        for (int o = 16; o > 0; o >>= 1)
            Z += __shfl_xor_sync(0xffffffffu, Z, o);
        if (lane == 0) {
            sM[w] = Mlogit;
            sInvZ[w] = 1.0f / Z;
            sS[w] = ss;
        }
    }
    __syncthreads();

    // ---- 3) chunked coef + paired fp32 gather with FFMA2 ----
    const int hh_t    = (t & 127) >> 4;     // head of my 8 columns
    const unsigned colbase = (unsigned)((t & 127) << 3);  // my 8 columns
    const int ksel    = t >> 7;             // which neighbor of each pair
    unsigned long long acc2[4] = {0ull, 0ull, 0ull, 0ull};  // 8 packed fp32

    for (int k0 = 0; k0 < deg; k0 += 64) {
        const int nk = min(64, deg - k0);
        // coef table: 512 slots, 2 per thread
#pragma unroll
        for (int r = 0; r < 2; r++) {
            const int s  = t + 256 * r;
            const int kk = s >> 3;
            const int hh = s & 7;
            if (kk < nk) {
                const int j = nbr[k0 + kk];
                float x = sS[hh] + g_sneigh[(hh << 12) + j];
                x = (x > 0.0f) ? x : ALPHA * x;
                coef[kk][hh] = __expf(x - sM[hh]) * sInvZ[hh];
            }
        }
        __syncthreads();

        for (int m = 0; m < nk; m += 4) {
            const int k1 = m + ksel;
            const int k2 = m + 2 + ksel;
            const bool p1 = (k1 < nk);
            const bool p2 = (k2 < nk);
            const int j1 = p1 ? nbr[k0 + k1] : 0;
            const int j2 = p2 ? nbr[k0 + k2] : 0;
            ulonglong2 q0 = make_ulonglong2(0ull, 0ull), q1 = q0, q2 = q0, q3 = q0;
            const float* f1p = g_feats + (((unsigned)j1) << 10) + colbase;
            const float* f2p = g_feats + (((unsigned)j2) << 10) + colbase;
            if (p1) {
                q0 = *reinterpret_cast<const ulonglong2*>(f1p);
                q1 = *reinterpret_cast<const ulonglong2*>(f1p + 4);
            }
            if (p2) {
                q2 = *reinterpret_cast<const ulonglong2*>(f2p);
                q3 = *reinterpret_cast<const ulonglong2*>(f2p + 4);
            }
            const float c1 = p1 ? coef[k1][hh_t] : 0.0f;
            const float c2 = p2 ? coef[k2][hh_t] : 0.0f;
            unsigned long long c1p, c2p;
            asm("mov.b64 %0, {%1, %1};" : "=l"(c1p) : "r"(__float_as_uint(c1)));
            asm("mov.b64 %0, {%1, %1};" : "=l"(c2p) : "r"(__float_as_uint(c2)));
            ffma2(acc2[0], q0.x, c1p);
            ffma2(acc2[1], q0.y, c1p);
            ffma2(acc2[2], q1.x, c1p);
            ffma2(acc2[3], q1.y, c1p);
            ffma2(acc2[0], q2.x, c2p);
            ffma2(acc2[1], q2.y, c2p);
            ffma2(acc2[2], q3.x, c2p);
            ffma2(acc2[3], q3.y, c2p);
        }
        __syncthreads();
    }

    // unpack accumulators
    float a[8];
#pragma unroll
    for (int q = 0; q < 4; q++) {
        unsigned lo, hi;
        asm("mov.b64 {%0, %1}, %2;" : "=r"(lo), "=r"(hi) : "l"(acc2[q]));
        a[2 * q]     = __uint_as_float(lo);
        a[2 * q + 1] = __uint_as_float(hi);
    }

    // cross-half reduction + epilogue
    if (t >= 128) {
#pragma unroll
        for (int q = 0; q < 8; q++) red[t - 128][q] = a[q];
    }
    __syncthreads();
    if (t < 128) {
        float4 b0 = *reinterpret_cast<const float4*>(bias + colbase);
        float4 b1 = *reinterpret_cast<const float4*>(bias + colbase + 4);
        float o0 = fmaxf(a[0] + red[t][0] + b0.x, 0.0f);
        float o1 = fmaxf(a[1] + red[t][1] + b0.y, 0.0f);
        float o2 = fmaxf(a[2] + red[t][2] + b0.z, 0.0f);
        float o3 = fmaxf(a[3] + red[t][3] + b0.w, 0.0f);
        float o4 = fmaxf(a[4] + red[t][4] + b1.x, 0.0f);
        float o5 = fmaxf(a[5] + red[t][5] + b1.y, 0.0f);
        float o6 = fmaxf(a[6] + red[t][6] + b1.z, 0.0f);
        float o7 = fmaxf(a[7] + red[t][7] + b1.w, 0.0f);
        float* dst = out + (size_t)i * HC + colbase;
        *reinterpret_cast<float4*>(dst)     = make_float4(o0, o1, o2, o3);
        *reinterpret_cast<float4*>(dst + 4) = make_float4(o4, o5, o6, o7);
    }
}

// ---------------------------------------------------------------------------
extern "C" void kernel_launch(void* const* d_in, const int* in_sizes, int n_in,
                              void* d_out, int out_size) {
    const float* X       = (const float*)d_in[0];  // [4096, 512]
    const float* A       = (const float*)d_in[1];  // [4096, 4096]
    const float* W       = (const float*)d_in[2];  // [8, 512, 128]
    const float* a_self  = (const float*)d_in[3];  // [8, 128]
    const float* a_neigh = (const float*)d_in[4];  // [8, 128]
    const float* bias    = (const float*)d_in[5];  // [8, 128]
    float* out = (float*)d_out;                    // [4096, 1024]

    gemm_kernel<<<dim3(H_HEADS, N_NODES / 128), 256>>>(X, W, a_self, a_neigh);
    agg_kernel<<<N_NODES, 256>>>(A, bias, out);
}

// round 10
// speedup vs baseline: 1.0866x; 1.0866x over previous
#include <cuda_runtime.h>
#include <cuda_fp16.h>
#include <math.h>

#define N_NODES 4096
#define F_IN 512
#define H_HEADS 8
#define C_OUT 128
#define HC (H_HEADS * C_OUT)   // 1024
#define ALPHA 0.2f
#define MAX_DEG 1024

// Scratch (allocation-free rule: __device__ globals)
__device__ __half g_feats_h[N_NODES * HC];    // [n][h*128+c], 8 MB (L2-resident)
__device__ float  g_sself[H_HEADS * N_NODES]; // [h][n]
__device__ float  g_sneigh[H_HEADS * N_NODES];// [h][n]

// ---------------------------------------------------------------------------
// TF32 tensor-core GEMM + fused score epilogue.
// grid (8, 64) = (head, m-tile). Block tile 64x128, BK=32, 256 threads.
// 8 warps as 2x4 -> warp tile 32x32, mma m16n8k8: 2x4 tiles per warp.
// Smem is FRAGMENT-MAJOR: each lane's mma fragment is contiguous
//   A: LDS.128 per (mt,ks);  B: LDS.64 per (nt,ks).
// Store-side bank conflicts broken by XOR swizzles undone at load
// (the XOR constant is uniform per load instruction -> lane permutation).
// ---------------------------------------------------------------------------
__device__ __forceinline__ unsigned f2tf32(float x) {
    unsigned u;
    asm("cvt.rna.tf32.f32 %0, %1;" : "=r"(u) : "f"(x));
    return u;
}

__device__ __forceinline__ void mma_tf32(float* c, const unsigned* a, const unsigned* b) {
    asm volatile(
        "mma.sync.aligned.m16n8k8.row.col.f32.tf32.tf32.f32 "
        "{%0,%1,%2,%3}, {%4,%5,%6,%7}, {%8,%9}, {%0,%1,%2,%3};"
        : "+f"(c[0]), "+f"(c[1]), "+f"(c[2]), "+f"(c[3])
        : "r"(a[0]), "r"(a[1]), "r"(a[2]), "r"(a[3]), "r"(b[0]), "r"(b[1]));
}

__global__ __launch_bounds__(256) void gemm_kernel(const float* __restrict__ X,
                                                   const float* __restrict__ W,
                                                   const float* __restrict__ a_self,
                                                   const float* __restrict__ a_neigh) {
    // A frags: [ks(4)][rb(4)][slot(32)][q(4)]  = 8 KB
    // B frags: [ks(4)][nb(16)][slot(32)][reg(2)] = 16 KB
    __shared__ unsigned As_f[4 * 4 * 32 * 4];
    __shared__ unsigned Bs_f[4 * 16 * 32 * 2];
    __shared__ float sredS[4][64];
    __shared__ float sredN[4][64];

    const int h  = blockIdx.x;
    const int m0 = blockIdx.y * 64;
    const float* Wh = W + (size_t)h * F_IN * C_OUT;

    const int t    = threadIdx.x;
    const int lane = t & 31;
    const int w    = t >> 5;
    const int warp_m = (w & 1) * 32;   // 0 or 32
    const int warp_n = (w >> 1) * 32;  // 0,32,64,96

    float acc[2][4][4];
#pragma unroll
    for (int mt = 0; mt < 2; mt++)
#pragma unroll
        for (int nt = 0; nt < 4; nt++)
#pragma unroll
            for (int q = 0; q < 4; q++) acc[mt][nt][q] = 0.0f;

    // Global-load indexing
    const int a_row  = t >> 3;        // 0..31 (+32*p, p=0..1)
    const int a_col4 = (t & 7) * 4;   // 0..28 (chunk-local)
    const int b_row  = t >> 5;        // 0..7 (+8*p, p=0..3)
    const int b_col4 = (t & 31) * 4;  // 0..124

    // Precomputed store descriptors
    const int a_ks = a_col4 >> 3;
    const int a_qc = (a_col4 & 4) >> 1;  // c-part of q
    const int b_nb = b_col4 >> 3;
    const int b_lb = (b_col4 & 4) << 2;  // n-part of slot

    float4 av[2], bv[4];
#pragma unroll
    for (int p = 0; p < 2; p++)
        av[p] = *reinterpret_cast<const float4*>(
            X + (size_t)(m0 + a_row + p * 32) * F_IN + a_col4);
#pragma unroll
    for (int p = 0; p < 4; p++)
        bv[p] = *reinterpret_cast<const float4*>(
            Wh + (size_t)(b_row + p * 8) * C_OUT + b_col4);

    for (int chunk = 0; chunk < F_IN / 32; chunk++) {
        __syncthreads();
        // ---- store A fragments ----
#pragma unroll
        for (int p = 0; p < 2; p++) {
            const int r  = a_row + p * 32;
            const int rb = r >> 4;
            const int Lb = (r & 7) << 2;
            const int q  = a_qc | ((r & 8) >> 3);
            const int base = (a_ks * 4 + rb) * 32;
            const float* vf = reinterpret_cast<const float*>(&av[p]);
#pragma unroll
            for (int u = 0; u < 4; u++) {
                const int PA = (Lb + u) ^ (a_ks << 1);
                As_f[(base + PA) * 4 + q] = f2tf32(vf[u]);
            }
        }
        // ---- store B fragments ----
#pragma unroll
        for (int p = 0; p < 4; p++) {
            const int k   = b_row + p * 8;
            const int ks  = k >> 3;
            const int reg = (k & 4) >> 2;
            const int Lb2 = b_lb | (k & 3);
            const int base = (ks * 16 + b_nb) * 32;
            const float* vf = reinterpret_cast<const float*>(&bv[p]);
#pragma unroll
            for (int u = 0; u < 4; u++) {
                const int PB = (Lb2 + (u << 2)) ^ b_nb;
                Bs_f[(base + PB) * 2 + reg] = f2tf32(vf[u]);
            }
        }
        __syncthreads();

        if (chunk + 1 < F_IN / 32) {
            const int k0 = (chunk + 1) * 32;
#pragma unroll
            for (int p = 0; p < 2; p++)
                av[p] = *reinterpret_cast<const float4*>(
                    X + (size_t)(m0 + a_row + p * 32) * F_IN + k0 + a_col4);
#pragma unroll
            for (int p = 0; p < 4; p++)
                bv[p] = *reinterpret_cast<const float4*>(
                    Wh + (size_t)(k0 + b_row + p * 8) * C_OUT + b_col4);
        }

#pragma unroll
        for (int ks = 0; ks < 4; ks++) {
            unsigned afr[2][4], bfr[4][2];
            const int PA = lane ^ (ks << 1);
#pragma unroll
            for (int mt = 0; mt < 2; mt++) {
                const int rb = (warp_m >> 4) + mt;
                const uint4 af = *reinterpret_cast<const uint4*>(
                    &As_f[((ks * 4 + rb) * 32 + PA) * 4]);
                afr[mt][0] = af.x; afr[mt][1] = af.y;
                afr[mt][2] = af.z; afr[mt][3] = af.w;
            }
#pragma unroll
            for (int nt = 0; nt < 4; nt++) {
                const int nb = (warp_n >> 3) + nt;
                const int PB = lane ^ nb;
                const uint2 bf = *reinterpret_cast<const uint2*>(
                    &Bs_f[((ks * 16 + nb) * 32 + PB) * 2]);
                bfr[nt][0] = bf.x; bfr[nt][1] = bf.y;
            }
#pragma unroll
            for (int mt = 0; mt < 2; mt++)
#pragma unroll
                for (int nt = 0; nt < 4; nt++)
                    mma_tf32(acc[mt][nt], afr[mt], bfr[nt]);
        }
    }

    // ---- Epilogue: fp16 feats store + fused score reduction ----
    const int rloc  = warp_m + (lane >> 2);
    const int cloc  = warp_n + (lane & 3) * 2;
    const int cbase = h * C_OUT + cloc;

    float asf[4][2], anf[4][2];
#pragma unroll
    for (int nt = 0; nt < 4; nt++) {
        float2 s2 = *reinterpret_cast<const float2*>(a_self  + h * C_OUT + cloc + nt * 8);
        float2 n2 = *reinterpret_cast<const float2*>(a_neigh + h * C_OUT + cloc + nt * 8);
        asf[nt][0] = s2.x; asf[nt][1] = s2.y;
        anf[nt][0] = n2.x; anf[nt][1] = n2.y;
    }

#pragma unroll
    for (int mt = 0; mt < 2; mt++) {
#pragma unroll
        for (int p = 0; p < 2; p++) {
            const int r = m0 + rloc + mt * 16 + p * 8;
            float ssp = 0.0f, snp = 0.0f;
#pragma unroll
            for (int nt = 0; nt < 4; nt++) {
                const float v0 = acc[mt][nt][2 * p];
                const float v1 = acc[mt][nt][2 * p + 1];
                ssp = fmaf(v0, asf[nt][0], ssp);
                ssp = fmaf(v1, asf[nt][1], ssp);
                snp = fmaf(v0, anf[nt][0], snp);
                snp = fmaf(v1, anf[nt][1], snp);
                __half2 hv = __floats2half2_rn(v0, v1);
                *reinterpret_cast<__half2*>(g_feats_h + (size_t)r * HC + cbase + nt * 8) = hv;
            }
            ssp += __shfl_xor_sync(0xffffffffu, ssp, 1);
            ssp += __shfl_xor_sync(0xffffffffu, ssp, 2);
            snp += __shfl_xor_sync(0xffffffffu, snp, 1);
            snp += __shfl_xor_sync(0xffffffffu, snp, 2);
            if ((lane & 3) == 0) {
                const int rl = rloc + mt * 16 + p * 8;  // 0..63
                sredS[w >> 1][rl] = ssp;
                sredN[w >> 1][rl] = snp;
            }
        }
    }
    __syncthreads();
    if (t < 64) {
        float ss = sredS[0][t] + sredS[1][t] + sredS[2][t] + sredS[3][t];
        float sn = sredN[0][t] + sredN[1][t] + sredN[2][t] + sredN[3][t];
        g_sself[h * N_NODES + m0 + t]  = ss;
        g_sneigh[h * N_NODES + m0 + t] = sn;
    }
}

// ---------------------------------------------------------------------------
// Aggregation: one CTA per row i.  (R8 fp16 gather + R9 compaction)
//  1) direct-to-position compaction: float4 A loads in regs, ballot-count,
//     warp prefix, write final positions (2 syncs, nbr[] only 1024)
//  2) per-head softmax stats (warp = head), __expf
//  3) 64-neighbor chunks: coef table, paired fp16 uint4 gather, fp32 acc
// ---------------------------------------------------------------------------
__global__ __launch_bounds__(256) void agg_kernel(const float* __restrict__ A,
                                                  const float* __restrict__ bias,
                                                  float* __restrict__ out) {
    __shared__ int   nbr[MAX_DEG];      // 4 KB
    __shared__ int   warp_cnt[8];
    __shared__ float sM[H_HEADS], sInvZ[H_HEADS], sS[H_HEADS];
    __shared__ float coef[64][H_HEADS]; // 2 KB
    __shared__ float red[128][8];       // 4 KB

    const int i    = blockIdx.x;
    const int t    = threadIdx.x;
    const int lane = t & 31;
    const int w    = t >> 5;

    const float* Arow = A + (size_t)i * N_NODES;

    // ---- 1) compaction: count first, then write at final position ----
    float4 v4[4];
    unsigned bal[16];
    {
        const float* Aseg = Arow + (w << 9);  // warp owns 512 cols
#pragma unroll
        for (int b = 0; b < 4; b++)
            v4[b] = reinterpret_cast<const float4*>(Aseg)[(b << 5) + lane];  // MLP=4x16B
        int wcnt = 0;
        const float* vf = reinterpret_cast<const float*>(v4);
#pragma unroll
        for (int s = 0; s < 16; s++) {
            const bool p = (vf[s] != 0.0f);
            bal[s] = __ballot_sync(0xffffffffu, p);
            wcnt += __popc(bal[s]);
        }
        if (lane == 0) warp_cnt[w] = wcnt;
    }
    __syncthreads();

    int pref[9];
    pref[0] = 0;
#pragma unroll
    for (int ww = 0; ww < 8; ww++) pref[ww + 1] = pref[ww] + warp_cnt[ww];
    const int deg = min(pref[8], MAX_DEG);  // >= 1 (self loop)

    {
        const unsigned lmask = (1u << lane) - 1u;
        int running = pref[w];
        const float* vf = reinterpret_cast<const float*>(v4);
#pragma unroll
        for (int s = 0; s < 16; s++) {
            const bool p = (vf[s] != 0.0f);
            if (p) {
                const int pos = running + __popc(bal[s] & lmask);
                const int col = (w << 9) + ((s >> 2) << 7) + (lane << 2) + (s & 3);
                if (pos < MAX_DEG) nbr[pos] = col;
            }
            running += __popc(bal[s]);
        }
    }
    __syncthreads();

    // ---- 2) per-head softmax stats; warp w handles head w ----
    {
        const float ss = g_sself[(w << 12) + i];
        const float* snh = g_sneigh + (w << 12);
        float mx = -INFINITY;
#pragma unroll 4
        for (int k = lane; k < deg; k += 32)
            mx = fmaxf(mx, snh[nbr[k]]);
#pragma unroll
        for (int o = 16; o > 0; o >>= 1)
            mx = fmaxf(mx, __shfl_xor_sync(0xffffffffu, mx, o));
        float e = ss + mx;
        const float Mlogit = (e > 0.0f) ? e : ALPHA * e;  // leaky monotone

        float Z = 0.0f;
#pragma unroll 4
        for (int k = lane; k < deg; k += 32) {
            float x = ss + snh[nbr[k]];
            x = (x > 0.0f) ? x : ALPHA * x;
            Z += __expf(x - Mlogit);
        }
#pragma unroll
        for (int o = 16; o > 0; o >>= 1)
            Z += __shfl_xor_sync(0xffffffffu, Z, o);
        if (lane == 0) {
            sM[w] = Mlogit;
            sInvZ[w] = 1.0f / Z;
            sS[w] = ss;
        }
    }
    __syncthreads();

    // ---- 3) chunked coef + paired fp16 gather ----
    const int hh_t    = (t & 127) >> 4;               // head of my 8 columns
    const unsigned colbase = (unsigned)((t & 127) << 3);  // my 8 columns
    const int ksel    = t >> 7;                       // which neighbor of each pair
    float acc[8];
#pragma unroll
    for (int q = 0; q < 8; q++) acc[q] = 0.0f;

    for (int k0 = 0; k0 < deg; k0 += 64) {
        const int nk = min(64, deg - k0);
        // coef table: 512 slots, 2 per thread
#pragma unroll
        for (int r = 0; r < 2; r++) {
            const int s  = t + 256 * r;
            const int kk = s >> 3;
            const int hh = s & 7;
            if (kk < nk) {
                const int j = nbr[k0 + kk];
                float x = sS[hh] + g_sneigh[(hh << 12) + j];
                x = (x > 0.0f) ? x : ALPHA * x;
                coef[kk][hh] = __expf(x - sM[hh]) * sInvZ[hh];
            }
        }
        __syncthreads();

        for (int m = 0; m < nk; m += 4) {
            const int k1 = m + ksel;
            const int k2 = m + 2 + ksel;
            const bool p1 = (k1 < nk);
            const bool p2 = (k2 < nk);
            const int j1 = p1 ? nbr[k0 + k1] : 0;
            const int j2 = p2 ? nbr[k0 + k2] : 0;
            uint4 v1 = make_uint4(0, 0, 0, 0), v2 = make_uint4(0, 0, 0, 0);
            if (p1) v1 = *reinterpret_cast<const uint4*>(
                g_feats_h + (((unsigned)j1) << 10) + colbase);
            if (p2) v2 = *reinterpret_cast<const uint4*>(
                g_feats_h + (((unsigned)j2) << 10) + colbase);
            const float c1 = p1 ? coef[k1][hh_t] : 0.0f;
            const float c2 = p2 ? coef[k2][hh_t] : 0.0f;
            {
                const float2 f0 = __half22float2(*reinterpret_cast<const __half2*>(&v1.x));
                const float2 f1 = __half22float2(*reinterpret_cast<const __half2*>(&v1.y));
                const float2 f2 = __half22float2(*reinterpret_cast<const __half2*>(&v1.z));
                const float2 f3 = __half22float2(*reinterpret_cast<const __half2*>(&v1.w));
                acc[0] = fmaf(c1, f0.x, acc[0]); acc[1] = fmaf(c1, f0.y, acc[1]);
                acc[2] = fmaf(c1, f1.x, acc[2]); acc[3] = fmaf(c1, f1.y, acc[3]);
                acc[4] = fmaf(c1, f2.x, acc[4]); acc[5] = fmaf(c1, f2.y, acc[5]);
                acc[6] = fmaf(c1, f3.x, acc[6]); acc[7] = fmaf(c1, f3.y, acc[7]);
            }
            {
                const float2 f0 = __half22float2(*reinterpret_cast<const __half2*>(&v2.x));
                const float2 f1 = __half22float2(*reinterpret_cast<const __half2*>(&v2.y));
                const float2 f2 = __half22float2(*reinterpret_cast<const __half2*>(&v2.z));
                const float2 f3 = __half22float2(*reinterpret_cast<const __half2*>(&v2.w));
                acc[0] = fmaf(c2, f0.x, acc[0]); acc[1] = fmaf(c2, f0.y, acc[1]);
                acc[2] = fmaf(c2, f1.x, acc[2]); acc[3] = fmaf(c2, f1.y, acc[3]);
                acc[4] = fmaf(c2, f2.x, acc[4]); acc[5] = fmaf(c2, f2.y, acc[5]);
                acc[6] = fmaf(c2, f3.x, acc[6]); acc[7] = fmaf(c2, f3.y, acc[7]);
            }
        }
        __syncthreads();
    }

    // cross-half reduction + epilogue
    if (t >= 128) {
#pragma unroll
        for (int q = 0; q < 8; q++) red[t - 128][q] = acc[q];
    }
    __syncthreads();
    if (t < 128) {
        float4 b0 = *reinterpret_cast<const float4*>(bias + colbase);
        float4 b1 = *reinterpret_cast<const float4*>(bias + colbase + 4);
        float o0 = fmaxf(acc[0] + red[t][0] + b0.x, 0.0f);
        float o1 = fmaxf(acc[1] + red[t][1] + b0.y, 0.0f);
        float o2 = fmaxf(acc[2] + red[t][2] + b0.z, 0.0f);
        float o3 = fmaxf(acc[3] + red[t][3] + b0.w, 0.0f);
        float o4 = fmaxf(acc[4] + red[t][4] + b1.x, 0.0f);
        float o5 = fmaxf(acc[5] + red[t][5] + b1.y, 0.0f);
        float o6 = fmaxf(acc[6] + red[t][6] + b1.z, 0.0f);
        float o7 = fmaxf(acc[7] + red[t][7] + b1.w, 0.0f);
        float* dst = out + (size_t)i * HC + colbase;
        *reinterpret_cast<float4*>(dst)     = make_float4(o0, o1, o2, o3);
        *reinterpret_cast<float4*>(dst + 4) = make_float4(o4, o5, o6, o7);
    }
}

// ---------------------------------------------------------------------------
extern "C" void kernel_launch(void* const* d_in, const int* in_sizes, int n_in,
                              void* d_out, int out_size) {
    const float* X       = (const float*)d_in[0];  // [4096, 512]
    const float* A       = (const float*)d_in[1];  // [4096, 4096]
    const float* W       = (const float*)d_in[2];  // [8, 512, 128]
    const float* a_self  = (const float*)d_in[3];  // [8, 128]
    const float* a_neigh = (const float*)d_in[4];  // [8, 128]
    const float* bias    = (const float*)d_in[5];  // [8, 128]
    float* out = (float*)d_out;                    // [4096, 1024]

    gemm_kernel<<<dim3(H_HEADS, N_NODES / 64), 256>>>(X, W, a_self, a_neigh);
    agg_kernel<<<N_NODES, 256>>>(A, bias, out);
}